// round 14
// baseline (speedup 1.0000x reference)
#include <cuda_runtime.h>
#include <cstdint>

// x [B=32, T=4096, N=256] float32 -> z same shape.
#define BB 32
#define TT 4096
#define NN 256
#define BN (BB * NN)          // 8192 chains
#define NP (BN / 2)           // 4096 chain-pairs
#define CHUNK 64
#define NC (TT / CHUNK)       // 64 chunks
#define REFR 5

#define SLICES 4
#define B_PER (BB / SLICES)                 // 8 batches per slice
#define P1_SLICE_THREADS (B_PER * (NN/2) * NC)   // 65536 -> 256 blocks
#define P1_SLICE_BLOCKS  (P1_SLICE_THREADS / 256)
#define P3_SLICE_THREADS (B_PER * NN * NC)       // 131072 -> 512 blocks
#define P3_SLICE_BLOCKS  (P3_SLICE_THREADS / 256)

// Static scratch (~6.5 MB, L2-resident)
__device__ ulonglong2 g_mask2[NC][NP];    // per-chain 64-bit sign masks (pairs)
__device__ uint2      g_map2[NC][NP];     // per-chain nibble-packed chunk map
__device__ uint8_t    g_qin[NC][BN];      // incoming q per (chunk, chain)

// Byte-level automaton LUTs (blockDim.x == 256) — pass1 blocks only.
__device__ __forceinline__ void build_luts(uint32_t* s_sel, uint64_t* s_byt) {
    const uint32_t b = threadIdx.x;
    uint32_t sel = 0; uint64_t byt = 0;
    for (int k = 0; k < 8; ++k) {
        int pos = k, last = -3;
        while (pos < 8) {
            uint32_t m = b >> pos;
            if (!m) break;
            int s = pos + __ffs((int)m) - 1;
            last = s;
            pos = s + REFR + 1;
        }
        int q = last - 2; if (q < 0) q = 0;
        sel |= (uint32_t)q << (4 * k);
        byt |= (uint64_t)q << (8 * k);
    }
    s_sel[b] = sel; s_byt[b] = byt;
    __syncthreads();
}

// byte-packed (2 regs) -> nibble-packed u32 (q values are all <= 7)
__device__ __forceinline__ uint32_t nib_compress(uint32_t lo, uint32_t hi) {
    uint32_t t1 = lo | (lo >> 4);
    uint32_t t2 = hi | (hi >> 4);
    return __byte_perm(t1, 0, 0x4420) | (__byte_perm(t2, 0, 0x4420) << 16);
}

// Pass-1 work for one thread: chain-pair 'pair' (global), chunk c.
// Plain loads (R10-proven; .cs hurt), PRMT byte-fold for the 6-state map.
__device__ __forceinline__ void p1_work(const float2* __restrict__ x2,
                                        int pair, int c,
                                        const uint32_t* s_sel,
                                        const uint64_t* s_byt) {
    int b  = pair >> 7;                        // / (NN/2)
    int np = pair & 127;
    const float2* px = x2 + ((size_t)b * TT + (size_t)c * CHUNK) * (NN / 2) + np;

    uint64_t m0 = 0, m1 = 0;
    uint32_t S0l, S0h, S1l, S1h;

    {   // byte 7 first (right fold: S = m7)
        uint32_t b0 = 0, b1 = 0;
#pragma unroll
        for (int i = 0; i < 8; ++i) {
            float2 v = px[(size_t)(56 + i) * (NN / 2)];
            if (v.x > 0.0f) b0 |= 1u << i;
            if (v.y > 0.0f) b1 |= 1u << i;
        }
        m0 |= (uint64_t)b0 << 56; m1 |= (uint64_t)b1 << 56;
        uint64_t t;
        t = s_byt[b0]; S0l = (uint32_t)t; S0h = (uint32_t)(t >> 32);
        t = s_byt[b1]; S1l = (uint32_t)t; S1h = (uint32_t)(t >> 32);
    }
#pragma unroll
    for (int j = 6; j >= 0; --j) {
        uint32_t b0 = 0, b1 = 0;
#pragma unroll
        for (int i = 0; i < 8; ++i) {
            float2 v = px[(size_t)(j * 8 + i) * (NN / 2)];
            if (v.x > 0.0f) b0 |= 1u << i;
            if (v.y > 0.0f) b1 |= 1u << i;
        }
        m0 |= (uint64_t)b0 << (8 * j);
        m1 |= (uint64_t)b1 << (8 * j);
        uint32_t sel, nl, nh;
        sel = s_sel[b0]; nl = __byte_perm(S0l, S0h, sel); nh = __byte_perm(S0l, S0h, sel >> 16); S0l = nl; S0h = nh;
        sel = s_sel[b1]; nl = __byte_perm(S1l, S1h, sel); nh = __byte_perm(S1l, S1h, sel >> 16); S1l = nl; S1h = nh;
    }

    g_mask2[c][pair] = make_ulonglong2(m0, m1);
    g_map2[c][pair]  = make_uint2(nib_compress(S0l, S0h), nib_compress(S1l, S1h));
}

// Pass-3 work for one thread: chain bn (global), chunk c. Register ffs rebuild
// + 64 scalar coalesced streaming stores (R10-proven shape).
__device__ __forceinline__ void p3_work(float* __restrict__ out, int bn, int c) {
    const uint64_t* mask_flat = (const uint64_t*)g_mask2;  // flat [NC][BN]
    const uint8_t*  qin_flat  = (const uint8_t*)g_qin;     // flat [NC][BN]

    uint64_t mask = mask_flat[c * BN + bn];
    int pos = qin_flat[c * BN + bn];

    uint64_t spikes = 0;
    while (pos < CHUNK) {
        uint64_t m = mask >> pos;
        if (!m) break;
        int s = pos + __ffsll((long long)m) - 1;
        spikes |= 1ull << s;
        pos = s + REFR + 1;
    }

    int b = bn >> 8;
    int n = bn & (NN - 1);
    float* po = out + ((size_t)b * TT + (size_t)c * CHUNK) * NN + n;
#pragma unroll 16
    for (int i = 0; i < CHUNK; ++i) {
        uint32_t bit = (uint32_t)(spikes >> i) & 1u;
        __stcs(po + (size_t)i * NN, (float)bit);
    }
}

// Combo kernel: first p1_blocks blocks run pass1 on slice s1; the remaining
// blocks run pass3 on slice s3. Both resident in one wave -> mixed R/W traffic.
__global__ void __launch_bounds__(256, 6) combo(const float2* __restrict__ x2,
                                                float* __restrict__ out,
                                                int s1, int s3, int p1_blocks) {
    if ((int)blockIdx.x < p1_blocks) {
        __shared__ uint32_t s_sel[256];
        __shared__ uint64_t s_byt[256];
        build_luts(s_sel, s_byt);
        int t      = blockIdx.x * 256 + threadIdx.x;   // 0 .. P1_SLICE_THREADS-1
        int pair_l = t & (B_PER * 128 - 1);            // 0 .. 1023
        int c      = t >> 10;
        int pair   = s1 * (B_PER * 128) + pair_l;      // global pair
        p1_work(x2, pair, c, s_sel, s_byt);
    } else {
        int t    = (blockIdx.x - p1_blocks) * 256 + threadIdx.x;  // 0 .. P3_SLICE_THREADS-1
        int bn_l = t & (B_PER * NN - 1);               // 0 .. 2047
        int c    = t >> 11;
        int bn   = s3 * (B_PER * NN) + bn_l;           // global chain
        p3_work(out, bn, c);
    }
}

// Pass 2 on one slice: chain the 64 nibble-packed chunk maps (L2-resident).
__global__ void __launch_bounds__(256) pass2_slice(int s) {
    int bn = s * (B_PER * NN) + blockIdx.x * 256 + threadIdx.x;
    const uint32_t* maps = (const uint32_t*)g_map2;   // flat [NC][BN]
    uint8_t* qin = (uint8_t*)g_qin;                   // flat [NC][BN]
    uint32_t q = 0;
#pragma unroll
    for (int base = 0; base < NC; base += 16) {
        uint32_t m[16];
#pragma unroll
        for (int j = 0; j < 16; ++j) m[j] = maps[(base + j) * BN + bn];
#pragma unroll
        for (int j = 0; j < 16; ++j) {
            qin[(base + j) * BN + bn] = (uint8_t)q;
            q = (m[j] >> (q * 4)) & 7u;
        }
    }
}

extern "C" void kernel_launch(void* const* d_in, const int* in_sizes, int n_in,
                              void* d_out, int out_size) {
    (void)in_sizes; (void)n_in; (void)out_size;
    const float2* x2 = (const float2*)d_in[0];
    float* out = (float*)d_out;

    const int threads = 256;
    const int p2_blocks = (B_PER * NN) / threads;          // 8

    // Software pipeline over 4 batch-slices:
    //   p1(s0) | p2(s0) | [p1(s1)+p3(s0)] | p2(s1) | ... | p3(s3)
    combo<<<P1_SLICE_BLOCKS, threads>>>(x2, out, 0, 0, P1_SLICE_BLOCKS); // p1(s0) only
    pass2_slice<<<p2_blocks, threads>>>(0);
    combo<<<P1_SLICE_BLOCKS + P3_SLICE_BLOCKS, threads>>>(x2, out, 1, 0, P1_SLICE_BLOCKS);
    pass2_slice<<<p2_blocks, threads>>>(1);
    combo<<<P1_SLICE_BLOCKS + P3_SLICE_BLOCKS, threads>>>(x2, out, 2, 1, P1_SLICE_BLOCKS);
    pass2_slice<<<p2_blocks, threads>>>(2);
    combo<<<P1_SLICE_BLOCKS + P3_SLICE_BLOCKS, threads>>>(x2, out, 3, 2, P1_SLICE_BLOCKS);
    pass2_slice<<<p2_blocks, threads>>>(3);
    combo<<<P3_SLICE_BLOCKS, threads>>>(x2, out, 0, 3, 0);               // p3(s3) only
}

// round 17
// speedup vs baseline: 1.0398x; 1.0398x over previous
#include <cuda_runtime.h>
#include <cstdint>

// x [B=32, T=4096, N=256] float32 -> z same shape.
#define BB 32
#define TT 4096
#define NN 256
#define BN (BB * NN)          // 8192 chains
#define NP (BN / 2)           // 4096 chain-pairs
#define CHUNK 64
#define NC (TT / CHUNK)       // 64 chunks
#define REFR 5

#define SLICES 4
#define B_PER (BB / SLICES)                      // 8 batches per slice
#define CH_PER (B_PER * NN)                      // 2048 chains per slice
#define P1_SLICE_BLOCKS ((B_PER * (NN/2) * NC) / 256)   // 256
#define P3_SLICE_BLOCKS ((B_PER * NN * NC) / 256)       // 512
#define P2_SLICE_BLOCKS (CH_PER / 8)                    // 256 (8 warps=8 chains/block)

// Static scratch (~6.5 MB, L2-resident)
__device__ ulonglong2 g_mask2[NC][NP];    // per-chain 64-bit sign masks (pairs)
__device__ uint2      g_map2[NC][NP];     // per-chain nibble-packed chunk map
__device__ uint8_t    g_qin[NC][BN];      // incoming q per (chunk, chain)

// Byte-level automaton LUTs (blockDim.x == 256) — pass1 blocks only.
__device__ __forceinline__ void build_luts(uint32_t* s_sel, uint64_t* s_byt) {
    const uint32_t b = threadIdx.x;
    uint32_t sel = 0; uint64_t byt = 0;
    for (int k = 0; k < 8; ++k) {
        int pos = k, last = -3;
        while (pos < 8) {
            uint32_t m = b >> pos;
            if (!m) break;
            int s = pos + __ffs((int)m) - 1;
            last = s;
            pos = s + REFR + 1;
        }
        int q = last - 2; if (q < 0) q = 0;
        sel |= (uint32_t)q << (4 * k);
        byt |= (uint64_t)q << (8 * k);
    }
    s_sel[b] = sel; s_byt[b] = byt;
    __syncthreads();
}

// byte-packed (2 regs) -> nibble-packed u32 (q values are all <= 7)
__device__ __forceinline__ uint32_t nib_compress(uint32_t lo, uint32_t hi) {
    uint32_t t1 = lo | (lo >> 4);
    uint32_t t2 = hi | (hi >> 4);
    return __byte_perm(t1, 0, 0x4420) | (__byte_perm(t2, 0, 0x4420) << 16);
}

// nibble-packed u32 -> byte-packed (2 regs)
__device__ __forceinline__ void nib_expand(uint32_t v, uint32_t& lo, uint32_t& hi) {
    uint32_t t = v & 0x0F0F0F0Fu;          // nibbles 0,2,4,6
    uint32_t u = (v >> 4) & 0x0F0F0F0Fu;   // nibbles 1,3,5,7
    lo = __byte_perm(t, u, 0x5140);        // [n0,n1,n2,n3]
    hi = __byte_perm(t, u, 0x7362);        // [n4,n5,n6,n7]
}

// Pass-1 work: chain-pair 'pair' (global), chunk c. Plain loads (proven),
// PRMT byte-fold for the 6-state map.
__device__ __forceinline__ void p1_work(const float2* __restrict__ x2,
                                        int pair, int c,
                                        const uint32_t* s_sel,
                                        const uint64_t* s_byt) {
    int b  = pair >> 7;                        // / (NN/2)
    int np = pair & 127;
    const float2* px = x2 + ((size_t)b * TT + (size_t)c * CHUNK) * (NN / 2) + np;

    uint64_t m0 = 0, m1 = 0;
    uint32_t S0l, S0h, S1l, S1h;

    {   // byte 7 first (right fold: S = m7)
        uint32_t b0 = 0, b1 = 0;
#pragma unroll
        for (int i = 0; i < 8; ++i) {
            float2 v = px[(size_t)(56 + i) * (NN / 2)];
            if (v.x > 0.0f) b0 |= 1u << i;
            if (v.y > 0.0f) b1 |= 1u << i;
        }
        m0 |= (uint64_t)b0 << 56; m1 |= (uint64_t)b1 << 56;
        uint64_t t;
        t = s_byt[b0]; S0l = (uint32_t)t; S0h = (uint32_t)(t >> 32);
        t = s_byt[b1]; S1l = (uint32_t)t; S1h = (uint32_t)(t >> 32);
    }
#pragma unroll
    for (int j = 6; j >= 0; --j) {
        uint32_t b0 = 0, b1 = 0;
#pragma unroll
        for (int i = 0; i < 8; ++i) {
            float2 v = px[(size_t)(j * 8 + i) * (NN / 2)];
            if (v.x > 0.0f) b0 |= 1u << i;
            if (v.y > 0.0f) b1 |= 1u << i;
        }
        m0 |= (uint64_t)b0 << (8 * j);
        m1 |= (uint64_t)b1 << (8 * j);
        uint32_t sel, nl, nh;
        sel = s_sel[b0]; nl = __byte_perm(S0l, S0h, sel); nh = __byte_perm(S0l, S0h, sel >> 16); S0l = nl; S0h = nh;
        sel = s_sel[b1]; nl = __byte_perm(S1l, S1h, sel); nh = __byte_perm(S1l, S1h, sel >> 16); S1l = nl; S1h = nh;
    }

    g_mask2[c][pair] = make_ulonglong2(m0, m1);
    g_map2[c][pair]  = make_uint2(nib_compress(S0l, S0h), nib_compress(S1l, S1h));
}

// Pass-3 work: chain bn (global), chunk c. Register ffs rebuild + 64 scalar
// coalesced streaming stores (proven shape).
__device__ __forceinline__ void p3_work(float* __restrict__ out, int bn, int c) {
    const uint64_t* mask_flat = (const uint64_t*)g_mask2;  // flat [NC][BN]
    const uint8_t*  qin_flat  = (const uint8_t*)g_qin;     // flat [NC][BN]

    uint64_t mask = mask_flat[c * BN + bn];
    int pos = qin_flat[c * BN + bn];

    uint64_t spikes = 0;
    while (pos < CHUNK) {
        uint64_t m = mask >> pos;
        if (!m) break;
        int s = pos + __ffsll((long long)m) - 1;
        spikes |= 1ull << s;
        pos = s + REFR + 1;
    }

    int b = bn >> 8;
    int n = bn & (NN - 1);
    float* po = out + ((size_t)b * TT + (size_t)c * CHUNK) * NN + n;
#pragma unroll 16
    for (int i = 0; i < CHUNK; ++i) {
        uint32_t bit = (uint32_t)(spikes >> i) & 1u;
        __stcs(po + (size_t)i * NN, (float)bit);
    }
}

// Combo kernel: first p1_blocks blocks run pass1 on slice s1; the remaining
// blocks run pass3 on slice s3. Both resident -> mixed R/W DRAM traffic.
__global__ void __launch_bounds__(256, 6) combo(const float2* __restrict__ x2,
                                                float* __restrict__ out,
                                                int s1, int s3, int p1_blocks) {
    if ((int)blockIdx.x < p1_blocks) {
        __shared__ uint32_t s_sel[256];
        __shared__ uint64_t s_byt[256];
        build_luts(s_sel, s_byt);
        int t      = blockIdx.x * 256 + threadIdx.x;
        int pair_l = t & (B_PER * 128 - 1);            // 0 .. 1023
        int c      = t >> 10;
        int pair   = s1 * (B_PER * 128) + pair_l;
        p1_work(x2, pair, c, s_sel, s_byt);
    } else {
        int t    = (blockIdx.x - p1_blocks) * 256 + threadIdx.x;
        int bn_l = t & (B_PER * NN - 1);               // 0 .. 2047
        int c    = t >> 11;
        int bn   = s3 * (B_PER * NN) + bn_l;
        p3_work(out, bn, c);
    }
}

// Pass 2 (warp-scan, FIXED): one warp per chain. Lane l holds chunks 2l, 2l+1.
// Representation discipline: byte-packed (P_lo,P_hi) is PRMT *data*;
// nibble-packed Pn is the PRMT *selector*. Only Pn is shuffled.
// Combine: new[k] = P_self[P_earlier[k]] -> PRMT(P_lo, P_hi, earlier_nibbles).
__global__ void __launch_bounds__(256) pass2_scan(int s) {
    __shared__ uint8_t s_q[8][64];                 // [chain-in-block][c]

    int lane = threadIdx.x & 31;
    int wib  = threadIdx.x >> 5;                   // warp (=chain) in block, 0..7
    int bn   = s * CH_PER + blockIdx.x * 8 + wib;  // global chain

    const uint32_t* maps = (const uint32_t*)g_map2;   // flat [NC][BN]

    uint32_t nm0 = maps[(2 * lane) * BN + bn];     // M(2l)   nibble-packed
    uint32_t nm1 = maps[(2 * lane + 1) * BN + bn]; // M(2l+1) nibble-packed

    // L = M(2l+1) ∘ M(2l): data = byte-packed M(2l+1), selector = nm0.
    uint32_t b_lo, b_hi;
    nib_expand(nm1, b_lo, b_hi);
    uint32_t P_lo = __byte_perm(b_lo, b_hi, nm0);
    uint32_t P_hi = __byte_perm(b_lo, b_hi, nm0 >> 16);
    uint32_t Pn   = nib_compress(P_lo, P_hi);

    // Inclusive scan: P(l) = L(l) ∘ ... ∘ L(0)
#pragma unroll
    for (int d = 1; d < 32; d <<= 1) {
        uint32_t en = __shfl_up_sync(0xFFFFFFFFu, Pn, d);  // earlier prefix (nibbles)
        if (lane >= d) {
            uint32_t nlo = __byte_perm(P_lo, P_hi, en);        // self[earlier[k]]
            uint32_t nhi = __byte_perm(P_lo, P_hi, en >> 16);
            P_lo = nlo; P_hi = nhi;
            Pn = nib_compress(P_lo, P_hi);
        }
    }

    // qin[2l] = P(l-1)[0] (0 for lane 0); qin[2l+1] = M(2l)[qin[2l]]
    uint32_t prev_n = __shfl_up_sync(0xFFFFFFFFu, Pn, 1);
    uint32_t q0 = (lane == 0) ? 0u : (prev_n & 7u);
    uint32_t q1 = (nm0 >> (4 * q0)) & 7u;

    s_q[wib][2 * lane]     = (uint8_t)q0;
    s_q[wib][2 * lane + 1] = (uint8_t)q1;
    __syncthreads();

    // Transpose out: thread t<64 packs the 8 chains' byte for c=t -> STG.64
    if (threadIdx.x < 64) {
        int c = threadIdx.x;
        uint64_t w = 0;
#pragma unroll
        for (int j = 0; j < 8; ++j)
            w |= (uint64_t)s_q[j][c] << (8 * j);
        int bn0 = s * CH_PER + blockIdx.x * 8;     // multiple of 8 -> aligned
        *(uint64_t*)((uint8_t*)g_qin + (size_t)c * BN + bn0) = w;
    }
}

extern "C" void kernel_launch(void* const* d_in, const int* in_sizes, int n_in,
                              void* d_out, int out_size) {
    (void)in_sizes; (void)n_in; (void)out_size;
    const float2* x2 = (const float2*)d_in[0];
    float* out = (float*)d_out;

    const int threads = 256;

    // Software pipeline over 4 batch-slices:
    //   p1(s0) | p2(s0) | [p1(s1)+p3(s0)] | p2(s1) | ... | p3(s3)
    combo<<<P1_SLICE_BLOCKS, threads>>>(x2, out, 0, 0, P1_SLICE_BLOCKS); // p1(s0) only
    pass2_scan<<<P2_SLICE_BLOCKS, threads>>>(0);
    combo<<<P1_SLICE_BLOCKS + P3_SLICE_BLOCKS, threads>>>(x2, out, 1, 0, P1_SLICE_BLOCKS);
    pass2_scan<<<P2_SLICE_BLOCKS, threads>>>(1);
    combo<<<P1_SLICE_BLOCKS + P3_SLICE_BLOCKS, threads>>>(x2, out, 2, 1, P1_SLICE_BLOCKS);
    pass2_scan<<<P2_SLICE_BLOCKS, threads>>>(2);
    combo<<<P1_SLICE_BLOCKS + P3_SLICE_BLOCKS, threads>>>(x2, out, 3, 2, P1_SLICE_BLOCKS);
    pass2_scan<<<P2_SLICE_BLOCKS, threads>>>(3);
    combo<<<P3_SLICE_BLOCKS, threads>>>(x2, out, 0, 3, 0);               // p3(s3) only
}